// round 1
// baseline (speedup 1.0000x reference)
#include <cuda_runtime.h>
#include <cstdint>

// GridNeRF forward, fused single kernel.
// Inputs (metadata order): x, v, o, table, dw1, db1, dw2, db2, rw1, rb1, rw2, rb2
// Output: [sigma (N)] ++ [rgb (N*3)] as float32.

constexpr int TSZ   = 1 << 19;   // hashmap entries per level
constexpr int DIN   = 47;        // 3 xyz + 36 fourier + 8 active grid feats
constexpr int DHID  = 64;

__global__ void __launch_bounds__(128) nerf_fwd_kernel(
    const float* __restrict__ x, const float* __restrict__ v,
    const float* __restrict__ table,
    const float* __restrict__ dw1, const float* __restrict__ db1,
    const float* __restrict__ dw2, const float* __restrict__ db2,
    const float* __restrict__ rw1, const float* __restrict__ rb1,
    const float* __restrict__ rw2, const float* __restrict__ rb2,
    float* __restrict__ out, int n)
{
    // ---- stage weights in shared (broadcast reads, LDS.128) ----
    __shared__ __align__(16) float s_w1[DIN * 64];     // rows 0..46 of dw1 (contiguous prefix)
    __shared__ __align__(16) float s_w2t[65 * 64];     // transposed: [j][m] = dw2[m][j]
    __shared__ __align__(16) float s_rw1[73 * 64];
    __shared__ __align__(16) float s_rw2t[3 * 64];     // transposed: [c][k] = rw2[k][c]
    __shared__ __align__(16) float s_b1[64];
    __shared__ __align__(16) float s_rb1[64];
    __shared__ __align__(16) float s_b2[68];           // 65 used, padded
    __shared__ float s_rb2[3];

    const int tid = threadIdx.x;
    for (int i = tid; i < DIN * 64; i += 128) s_w1[i] = dw1[i];
    for (int i = tid; i < 65 * 64; i += 128) {
        int j = i >> 6, m = i & 63;
        s_w2t[i] = dw2[m * 65 + j];
    }
    for (int i = tid; i < 73 * 64; i += 128) s_rw1[i] = rw1[i];
    for (int i = tid; i < 3 * 64; i += 128) {
        int c = i >> 6, k = i & 63;
        s_rw2t[i] = rw2[k * 3 + c];
    }
    if (tid < 64) { s_b1[tid] = db1[tid]; s_rb1[tid] = rb1[tid]; }
    if (tid < 65) s_b2[tid] = db2[tid];
    if (tid < 3)  s_rb2[tid] = rb2[tid];
    __syncthreads();

    const int i = blockIdx.x * 128 + tid;
    if (i >= n) return;

    const float px0 = x[3 * i + 0];
    const float px1 = x[3 * i + 1];
    const float px2 = x[3 * i + 2];

    // ---- build encoding vector (47 active dims) ----
    float xe[DIN];
    xe[0] = px0; xe[1] = px1; xe[2] = px2;

    // fourier: per dim d, 6 sins then 6 cosines of x_d * 2^f
    #pragma unroll
    for (int d = 0; d < 3; d++) {
        const float pv = (d == 0) ? px0 : ((d == 1) ? px1 : px2);
        float fm = 1.0f;
        #pragma unroll
        for (int fr = 0; fr < 6; fr++) {
            float s, c;
            sincosf(pv * fm, &s, &c);
            xe[3 + d * 12 + fr]     = s;
            xe[3 + d * 12 + 6 + fr] = c;
            fm *= 2.0f;
        }
    }

    // hashgrid, active levels 0..3 only (progressive mask zeroes the rest)
    {
        const float x01x = (px0 + 1.0f) * 0.5f;
        const float x01y = (px1 + 1.0f) * 0.5f;
        const float x01z = (px2 + 1.0f) * 0.5f;
        const float resf[4] = {33.0f, 43.0f, 56.0f, 74.0f};
        #pragma unroll
        for (int lv = 0; lv < 4; lv++) {
            const float pxx = x01x * resf[lv];
            const float pyy = x01y * resf[lv];
            const float pzz = x01z * resf[lv];
            const float fx = floorf(pxx), fy = floorf(pyy), fz = floorf(pzz);
            const float tx = pxx - fx,   ty = pyy - fy,   tz = pzz - fz;
            const float wx = tx * tx * (3.0f - 2.0f * tx);
            const float wy = ty * ty * (3.0f - 2.0f * ty);
            const float wz = tz * tz * (3.0f - 2.0f * tz);
            const unsigned cx = (unsigned)fx, cy = (unsigned)fy, cz = (unsigned)fz;
            const float* tb = table + (size_t)lv * (TSZ * 2);
            float f0 = 0.0f, f1 = 0.0f;
            #pragma unroll
            for (int c = 0; c < 8; c++) {
                const unsigned hx = cx + (c & 1);
                const unsigned hy = cy + ((c >> 1) & 1);
                const unsigned hz = cz + ((c >> 2) & 1);
                const unsigned h = (hx ^ (hy * 2654435761u) ^ (hz * 805459861u)) & (unsigned)(TSZ - 1);
                const float cw = ((c & 1)        ? wx : 1.0f - wx)
                               * (((c >> 1) & 1) ? wy : 1.0f - wy)
                               * (((c >> 2) & 1) ? wz : 1.0f - wz);
                const float2 tv = *reinterpret_cast<const float2*>(tb + 2u * h);
                f0 = fmaf(tv.x, cw, f0);
                f1 = fmaf(tv.y, cw, f1);
            }
            xe[39 + 2 * lv] = f0;
            xe[40 + 2 * lv] = f1;
        }
    }

    // ---- MLP1: h = relu(xe @ w1[0:47] + b1) ----
    float h[DHID];
    #pragma unroll
    for (int j = 0; j < DHID; j += 4) {
        const float4 b = *reinterpret_cast<const float4*>(&s_b1[j]);
        h[j] = b.x; h[j + 1] = b.y; h[j + 2] = b.z; h[j + 3] = b.w;
    }
    #pragma unroll
    for (int k = 0; k < DIN; k++) {
        const float xv = xe[k];
        const float4* wr = reinterpret_cast<const float4*>(&s_w1[k * 64]);
        #pragma unroll
        for (int jj = 0; jj < 16; jj++) {
            const float4 w = wr[jj];
            h[4 * jj + 0] = fmaf(xv, w.x, h[4 * jj + 0]);
            h[4 * jj + 1] = fmaf(xv, w.y, h[4 * jj + 1]);
            h[4 * jj + 2] = fmaf(xv, w.z, h[4 * jj + 2]);
            h[4 * jj + 3] = fmaf(xv, w.w, h[4 * jj + 3]);
        }
    }
    #pragma unroll
    for (int j = 0; j < DHID; j++) h[j] = fmaxf(h[j], 0.0f);

    // ---- sigma head: dout[0] = b2[0] + h . w2t[0] ----
    float sigma;
    {
        float a0 = s_b2[0], a1 = 0.0f, a2 = 0.0f, a3 = 0.0f;
        const float4* wr = reinterpret_cast<const float4*>(&s_w2t[0]);
        #pragma unroll
        for (int mm = 0; mm < 16; mm++) {
            const float4 w = wr[mm];
            a0 = fmaf(h[4 * mm + 0], w.x, a0);
            a1 = fmaf(h[4 * mm + 1], w.y, a1);
            a2 = fmaf(h[4 * mm + 2], w.z, a2);
            a3 = fmaf(h[4 * mm + 3], w.w, a3);
        }
        sigma = expf((a0 + a1) + (a2 + a3));
    }

    // ---- rgb net accumulators: hr = rb1 + sh3(v) @ rw1[64:73] ----
    float hr[DHID];
    #pragma unroll
    for (int j = 0; j < DHID; j += 4) {
        const float4 b = *reinterpret_cast<const float4*>(&s_rb1[j]);
        hr[j] = b.x; hr[j + 1] = b.y; hr[j + 2] = b.z; hr[j + 3] = b.w;
    }
    {
        const float vx = v[3 * i + 0];
        const float vy = v[3 * i + 1];
        const float vz = v[3 * i + 2];
        float sh[9];
        sh[0] = 0.28209479177387814f;
        sh[1] = -0.4886025119029199f * vy;
        sh[2] =  0.4886025119029199f * vz;
        sh[3] = -0.4886025119029199f * vx;
        sh[4] =  1.0925484305920792f * vx * vy;
        sh[5] = -1.0925484305920792f * vy * vz;
        sh[6] =  0.9461746957575601f * vz * vz - 0.31539156525252005f;
        sh[7] = -1.0925484305920792f * vx * vz;
        sh[8] =  0.5462742152960396f * (vx * vx - vy * vy);
        #pragma unroll
        for (int k = 0; k < 9; k++) {
            const float sv = sh[k];
            const float4* wr = reinterpret_cast<const float4*>(&s_rw1[(64 + k) * 64]);
            #pragma unroll
            for (int jj = 0; jj < 16; jj++) {
                const float4 w = wr[jj];
                hr[4 * jj + 0] = fmaf(sv, w.x, hr[4 * jj + 0]);
                hr[4 * jj + 1] = fmaf(sv, w.y, hr[4 * jj + 1]);
                hr[4 * jj + 2] = fmaf(sv, w.z, hr[4 * jj + 2]);
                hr[4 * jj + 3] = fmaf(sv, w.w, hr[4 * jj + 3]);
            }
        }
    }

    // ---- fused MLP2 tail + MLP3: feat[k] = relu(b2[k+1] + h . w2t[k+1]); hr += feat[k] * rw1[k] ----
    #pragma unroll
    for (int k = 0; k < DHID; k++) {
        float a0 = s_b2[k + 1], a1 = 0.0f, a2 = 0.0f, a3 = 0.0f;
        const float4* wr = reinterpret_cast<const float4*>(&s_w2t[(k + 1) * 64]);
        #pragma unroll
        for (int mm = 0; mm < 16; mm++) {
            const float4 w = wr[mm];
            a0 = fmaf(h[4 * mm + 0], w.x, a0);
            a1 = fmaf(h[4 * mm + 1], w.y, a1);
            a2 = fmaf(h[4 * mm + 2], w.z, a2);
            a3 = fmaf(h[4 * mm + 3], w.w, a3);
        }
        const float feat = fmaxf((a0 + a1) + (a2 + a3), 0.0f);
        const float4* wr2 = reinterpret_cast<const float4*>(&s_rw1[k * 64]);
        #pragma unroll
        for (int jj = 0; jj < 16; jj++) {
            const float4 w = wr2[jj];
            hr[4 * jj + 0] = fmaf(feat, w.x, hr[4 * jj + 0]);
            hr[4 * jj + 1] = fmaf(feat, w.y, hr[4 * jj + 1]);
            hr[4 * jj + 2] = fmaf(feat, w.z, hr[4 * jj + 2]);
            hr[4 * jj + 3] = fmaf(feat, w.w, hr[4 * jj + 3]);
        }
    }
    #pragma unroll
    for (int j = 0; j < DHID; j++) hr[j] = fmaxf(hr[j], 0.0f);

    // ---- MLP4: rgb = sigmoid(hr @ rw2 + rb2) ----
    float rgb[3];
    #pragma unroll
    for (int c = 0; c < 3; c++) {
        float a0 = s_rb2[c], a1 = 0.0f, a2 = 0.0f, a3 = 0.0f;
        const float4* wr = reinterpret_cast<const float4*>(&s_rw2t[c * 64]);
        #pragma unroll
        for (int kk = 0; kk < 16; kk++) {
            const float4 w = wr[kk];
            a0 = fmaf(hr[4 * kk + 0], w.x, a0);
            a1 = fmaf(hr[4 * kk + 1], w.y, a1);
            a2 = fmaf(hr[4 * kk + 2], w.z, a2);
            a3 = fmaf(hr[4 * kk + 3], w.w, a3);
        }
        const float z = (a0 + a1) + (a2 + a3);
        rgb[c] = 1.0f / (1.0f + expf(-z));
    }

    // ---- output: sigma [N], then rgb [N,3] ----
    out[i] = sigma;
    out[n + 3 * i + 0] = rgb[0];
    out[n + 3 * i + 1] = rgb[1];
    out[n + 3 * i + 2] = rgb[2];
}

extern "C" void kernel_launch(void* const* d_in, const int* in_sizes, int n_in,
                              void* d_out, int out_size)
{
    const float* x     = (const float*)d_in[0];
    const float* v     = (const float*)d_in[1];
    // d_in[2] = o (unused by forward)
    const float* table = (const float*)d_in[3];
    const float* dw1   = (const float*)d_in[4];
    const float* db1   = (const float*)d_in[5];
    const float* dw2   = (const float*)d_in[6];
    const float* db2   = (const float*)d_in[7];
    const float* rw1   = (const float*)d_in[8];
    const float* rb1   = (const float*)d_in[9];
    const float* rw2   = (const float*)d_in[10];
    const float* rb2   = (const float*)d_in[11];
    float* out = (float*)d_out;

    const int n = in_sizes[0] / 3;
    const int blocks = (n + 127) / 128;
    nerf_fwd_kernel<<<blocks, 128>>>(x, v, table, dw1, db1, dw2, db2,
                                     rw1, rb1, rw2, rb2, out, n);
}

// round 2
// speedup vs baseline: 1.6309x; 1.6309x over previous
#include <cuda_runtime.h>
#include <cstdint>

// GridNeRF forward, split into two kernels with f32x2 packed FMA.
// Inputs (metadata order): x, v, o, table, dw1, db1, dw2, db2, rw1, rb1, rw2, rb2
// Output: [sigma (N)] ++ [rgb (N*3)] as float32.

constexpr int TSZ  = 1 << 19;
constexpr int MAXN = 524288;

// scratch: relu'd feat, layout [k][point] for coalesced access
__device__ __align__(16) float g_feat[(size_t)MAXN * 64];

using ull = unsigned long long;

__device__ __forceinline__ ull pack2(float lo, float hi) {
    ull r; asm("mov.b64 %0, {%1, %2};" : "=l"(r) : "f"(lo), "f"(hi)); return r;
}
__device__ __forceinline__ float2 unpack2(ull v) {
    float2 r; asm("mov.b64 {%0, %1}, %2;" : "=f"(r.x), "=f"(r.y) : "l"(v)); return r;
}
__device__ __forceinline__ void ffma2(ull& d, ull a, ull b) {
    asm("fma.rn.f32x2 %0, %1, %2, %0;" : "+l"(d) : "l"(a), "l"(b));
}

// acc[0..31] (64 outputs packed) += dup(xv) * wrow[0..63]
__device__ __forceinline__ void rank1(ull* acc, const float* wrow, float xv) {
    const ull xd = pack2(xv, xv);
    const ulonglong2* w = reinterpret_cast<const ulonglong2*>(wrow);
    #pragma unroll
    for (int q = 0; q < 16; q++) {
        ulonglong2 ww = w[q];
        ffma2(acc[2 * q],     xd, ww.x);
        ffma2(acc[2 * q + 1], xd, ww.y);
    }
}

// dot of 64-packed h2 with 64-float row
__device__ __forceinline__ float dot64(const ull* h2, const float* wrow) {
    ull a0 = 0ull, a1 = 0ull, a2 = 0ull, a3 = 0ull;
    const ulonglong2* w = reinterpret_cast<const ulonglong2*>(wrow);
    #pragma unroll
    for (int q = 0; q < 8; q++) {
        ulonglong2 wa = w[2 * q];
        ulonglong2 wb = w[2 * q + 1];
        ffma2(a0, h2[4 * q],     wa.x);
        ffma2(a1, h2[4 * q + 1], wa.y);
        ffma2(a2, h2[4 * q + 2], wb.x);
        ffma2(a3, h2[4 * q + 3], wb.y);
    }
    float2 f0 = unpack2(a0), f1 = unpack2(a1), f2 = unpack2(a2), f3 = unpack2(a3);
    return ((f0.x + f0.y) + (f1.x + f1.y)) + ((f2.x + f2.y) + (f3.x + f3.y));
}

// ===================== Kernel A: encode + MLP1 + MLP2 =====================
__global__ void __launch_bounds__(128, 4) nerf_kA(
    const float* __restrict__ x, const float* __restrict__ table,
    const float* __restrict__ dw1, const float* __restrict__ db1,
    const float* __restrict__ dw2, const float* __restrict__ db2,
    float* __restrict__ out, int n)
{
    __shared__ __align__(16) float s_w1[47 * 64];
    __shared__ __align__(16) float s_w2t[65 * 64];   // [j][m] = dw2[m][j]
    __shared__ __align__(16) float s_b1[64];
    __shared__ float s_b2[66];

    const int tid = threadIdx.x;
    for (int idx = tid; idx < 47 * 64; idx += 128) s_w1[idx] = dw1[idx];
    for (int idx = tid; idx < 65 * 64; idx += 128) {      // coalesced read, scattered smem write
        int m = idx / 65, j = idx % 65;
        s_w2t[j * 64 + m] = dw2[idx];
    }
    if (tid < 64) s_b1[tid] = db1[tid];
    if (tid < 65) s_b2[tid] = db2[tid];
    __syncthreads();

    const int i = blockIdx.x * 128 + tid;
    if (i >= n) return;

    const float px0 = x[3 * i + 0];
    const float px1 = x[3 * i + 1];
    const float px2 = x[3 * i + 2];
    float px[3] = {px0, px1, px2};

    // h accumulators, packed pairs, init with bias
    ull h2[32];
    #pragma unroll
    for (int q = 0; q < 32; q++) h2[q] = pack2(s_b1[2 * q], s_b1[2 * q + 1]);

    // rows 0..2: xyz
    rank1(h2, s_w1 + 0 * 64, px0);
    rank1(h2, s_w1 + 1 * 64, px1);
    rank1(h2, s_w1 + 2 * 64, px2);

    // rows 3..38: fourier (per dim: 6 sins, then 6 cosines)
    #pragma unroll
    for (int d = 0; d < 3; d++) {
        float cbuf[6];
        float fm = 1.0f;
        #pragma unroll
        for (int fr = 0; fr < 6; fr++) {
            float s, c;
            __sincosf(px[d] * fm, &s, &c);
            rank1(h2, s_w1 + (3 + d * 12 + fr) * 64, s);
            cbuf[fr] = c;
            fm *= 2.0f;
        }
        #pragma unroll
        for (int fr = 0; fr < 6; fr++)
            rank1(h2, s_w1 + (3 + d * 12 + 6 + fr) * 64, cbuf[fr]);
    }

    // rows 39..46: hashgrid, active levels 0..3 (progressive mask kills the rest)
    {
        const float x01x = (px0 + 1.0f) * 0.5f;
        const float x01y = (px1 + 1.0f) * 0.5f;
        const float x01z = (px2 + 1.0f) * 0.5f;
        const float resf[4] = {33.0f, 43.0f, 56.0f, 74.0f};
        #pragma unroll
        for (int lv = 0; lv < 4; lv++) {
            const float pxx = x01x * resf[lv];
            const float pyy = x01y * resf[lv];
            const float pzz = x01z * resf[lv];
            const float fx = floorf(pxx), fy = floorf(pyy), fz = floorf(pzz);
            const float tx = pxx - fx,   ty = pyy - fy,   tz = pzz - fz;
            const float wx = tx * tx * (3.0f - 2.0f * tx);
            const float wy = ty * ty * (3.0f - 2.0f * ty);
            const float wz = tz * tz * (3.0f - 2.0f * tz);
            const unsigned cx = (unsigned)fx, cy = (unsigned)fy, cz = (unsigned)fz;
            const float* tb = table + (size_t)lv * (TSZ * 2);
            float f0 = 0.0f, f1 = 0.0f;
            #pragma unroll
            for (int c = 0; c < 8; c++) {
                const unsigned hx = cx + (c & 1);
                const unsigned hy = cy + ((c >> 1) & 1);
                const unsigned hz = cz + ((c >> 2) & 1);
                const unsigned hsh = (hx ^ (hy * 2654435761u) ^ (hz * 805459861u)) & (unsigned)(TSZ - 1);
                const float cw = ((c & 1)        ? wx : 1.0f - wx)
                               * (((c >> 1) & 1) ? wy : 1.0f - wy)
                               * (((c >> 2) & 1) ? wz : 1.0f - wz);
                const float2 tv = __ldg(reinterpret_cast<const float2*>(tb + 2u * hsh));
                f0 = fmaf(tv.x, cw, f0);
                f1 = fmaf(tv.y, cw, f1);
            }
            rank1(h2, s_w1 + (39 + 2 * lv) * 64, f0);
            rank1(h2, s_w1 + (40 + 2 * lv) * 64, f1);
        }
    }

    // relu h
    #pragma unroll
    for (int q = 0; q < 32; q++) {
        float2 t = unpack2(h2[q]);
        h2[q] = pack2(fmaxf(t.x, 0.0f), fmaxf(t.y, 0.0f));
    }

    // sigma head (j=0)
    out[i] = __expf(s_b2[0] + dot64(h2, s_w2t));

    // feat heads (j=1..64), relu, store [k][pt] coalesced
    float* gp = g_feat + i;
    #pragma unroll 4
    for (int j = 1; j <= 64; j++) {
        float f = fmaxf(s_b2[j] + dot64(h2, s_w2t + j * 64), 0.0f);
        *gp = f;
        gp += n;
    }
}

// ===================== Kernel B: SH + MLP3 + MLP4 =====================
__global__ void __launch_bounds__(128, 4) nerf_kB(
    const float* __restrict__ v,
    const float* __restrict__ rw1, const float* __restrict__ rb1,
    const float* __restrict__ rw2, const float* __restrict__ rb2,
    float* __restrict__ out, int n)
{
    __shared__ __align__(16) float s_rw1[73 * 64];
    __shared__ __align__(16) float s_rw2t[3 * 64];   // [c][k] = rw2[k][c]
    __shared__ __align__(16) float s_rb1[64];
    __shared__ float s_rb2[3];

    const int tid = threadIdx.x;
    for (int idx = tid; idx < 73 * 64; idx += 128) s_rw1[idx] = rw1[idx];
    for (int idx = tid; idx < 3 * 64; idx += 128) {
        int k = idx / 3, c = idx % 3;
        s_rw2t[c * 64 + k] = rw2[idx];
    }
    if (tid < 64) s_rb1[tid] = rb1[tid];
    if (tid < 3)  s_rb2[tid] = rb2[tid];
    __syncthreads();

    const int i = blockIdx.x * 128 + tid;
    if (i >= n) return;

    ull hr2[32];
    #pragma unroll
    for (int q = 0; q < 32; q++) hr2[q] = pack2(s_rb1[2 * q], s_rb1[2 * q + 1]);

    // spherical harmonics contribution (rows 64..72 of rw1)
    {
        const float vx = v[3 * i + 0];
        const float vy = v[3 * i + 1];
        const float vz = v[3 * i + 2];
        float sh[9];
        sh[0] = 0.28209479177387814f;
        sh[1] = -0.4886025119029199f * vy;
        sh[2] =  0.4886025119029199f * vz;
        sh[3] = -0.4886025119029199f * vx;
        sh[4] =  1.0925484305920792f * vx * vy;
        sh[5] = -1.0925484305920792f * vy * vz;
        sh[6] =  0.9461746957575601f * vz * vz - 0.31539156525252005f;
        sh[7] = -1.0925484305920792f * vx * vz;
        sh[8] =  0.5462742152960396f * (vx * vx - vy * vy);
        #pragma unroll
        for (int k = 0; k < 9; k++)
            rank1(hr2, s_rw1 + (64 + k) * 64, sh[k]);
    }

    // stream feats (rows 0..63 of rw1), prefetch in groups of 8
    const float* gp = g_feat + i;
    #pragma unroll
    for (int k0 = 0; k0 < 64; k0 += 8) {
        float fb[8];
        #pragma unroll
        for (int u = 0; u < 8; u++)
            fb[u] = gp[(size_t)(k0 + u) * n];
        #pragma unroll
        for (int u = 0; u < 8; u++)
            rank1(hr2, s_rw1 + (k0 + u) * 64, fb[u]);
    }

    // relu hr
    #pragma unroll
    for (int q = 0; q < 32; q++) {
        float2 t = unpack2(hr2[q]);
        hr2[q] = pack2(fmaxf(t.x, 0.0f), fmaxf(t.y, 0.0f));
    }

    // MLP4 + sigmoid
    #pragma unroll
    for (int c = 0; c < 3; c++) {
        float z = s_rb2[c] + dot64(hr2, s_rw2t + c * 64);
        out[n + 3 * i + c] = 1.0f / (1.0f + __expf(-z));
    }
}

extern "C" void kernel_launch(void* const* d_in, const int* in_sizes, int n_in,
                              void* d_out, int out_size)
{
    const float* x     = (const float*)d_in[0];
    const float* v     = (const float*)d_in[1];
    const float* table = (const float*)d_in[3];
    const float* dw1   = (const float*)d_in[4];
    const float* db1   = (const float*)d_in[5];
    const float* dw2   = (const float*)d_in[6];
    const float* db2   = (const float*)d_in[7];
    const float* rw1   = (const float*)d_in[8];
    const float* rb1   = (const float*)d_in[9];
    const float* rw2   = (const float*)d_in[10];
    const float* rb2   = (const float*)d_in[11];
    float* out = (float*)d_out;

    int n = in_sizes[0] / 3;
    if (n > MAXN) n = MAXN;
    const int blocks = (n + 127) / 128;
    nerf_kA<<<blocks, 128>>>(x, table, dw1, db1, dw2, db2, out, n);
    nerf_kB<<<blocks, 128>>>(v, rw1, rb1, rw2, rb2, out, n);
}